// round 10
// baseline (speedup 1.0000x reference)
#include <cuda_runtime.h>
#include <cuda_fp16.h>
#include <cstdint>

// ============================================================
// Problem dims (fixed per reference)
// ============================================================
#define M_TOTAL 16384   // B*S (m)
#define O_TOTAL 4096    // D_OUT (o)
#define K_TOTAL 4096    // D_IN (k)

// Sparse GEMM tile: CTA = 128 o x 128 m, BK=64 (2 x k32 chunks)
#define BO 128
#define BMM 128
#define BK 64
#define STAGES 3
#define KITERS (K_TOTAL / BK)          // 64
#define GRID_O (O_TOTAL / BO)          // 32
#define GRID_M (M_TOTAL / BMM)         // 128
#define NTHREADS 128                   // 4 warps: 2(o) x 2(m), warp tile 64x64

// smem stage layout
#define X_ROW_BYTES 144                // 64 halves + 8 pad
#define X_STAGE_BYTES (BMM * X_ROW_BYTES)          // 18432
#define WV_ROW_BYTES 80                // 32 stored halves + 8 pad
#define WV_STAGE_BYTES (BO * WV_ROW_BYTES)         // 10240
#define ME_STAGE_BYTES 2048            // 8 o-groups x 2 chunks x 32 lanes x 4B
#define STAGE_BYTES (X_STAGE_BYTES + WV_STAGE_BYTES + ME_STAGE_BYTES)  // 30720
#define SMEM_BIAS_BYTES 1024
#define SMEM_TOTAL (SMEM_BIAS_BYTES + STAGES * STAGE_BYTES)   // 93184 (x2 CTA <= 228KB)
#define EPI_PITCH 132                  // staging[m][o] floats, 16B-aligned rows

// residual buckets (o-range of 128 each)
#define RES_BUCKETS 32
#define RES_CAP 8192

// ------------------------------------------------------------
// static device scratch (no runtime alloc)
// ------------------------------------------------------------
__device__ __align__(1024) __half   g_xh[(size_t)M_TOTAL * K_TOTAL];   // x fp16 [m][k]
__device__ __align__(1024) __half   g_xt[(size_t)K_TOTAL * M_TOTAL];   // x^T fp16 [k][m]
__device__ __align__(1024) __half   g_wv[(size_t)O_TOTAL * (K_TOTAL/2)]; // 2:4 values [o][k/2]
__device__ __align__(1024) uint32_t g_wm[(size_t)(O_TOTAL/16) * (K_TOTAL/32) * 32]; // metadata
__device__ uint8_t g_meta4[(size_t)O_TOTAL * (K_TOTAL/4)];             // per-group 4-bit codes
__device__ uint2   g_res[RES_BUCKETS * RES_CAP];                       // {o_l | k<<7, fp32 bits}
__device__ int     g_res_cnt[RES_BUCKETS];

// ============================================================
// PTX helpers (sm_80 base ISA — safe under compute_103)
// ============================================================
__device__ __forceinline__ uint32_t smem_to_u32(const void* p) {
    uint32_t a;
    asm("{ .reg .u64 t; cvta.to.shared.u64 t, %1; cvt.u32.u64 %0, t; }" : "=r"(a) : "l"(p));
    return a;
}
__device__ __forceinline__ void cp_async16(uint32_t saddr, const void* gptr) {
    asm volatile("cp.async.cg.shared.global [%0], [%1], 16;" :: "r"(saddr), "l"(gptr));
}
__device__ __forceinline__ void cp_commit() { asm volatile("cp.async.commit_group;"); }
template <int N>
__device__ __forceinline__ void cp_wait_group() {
    asm volatile("cp.async.wait_group %0;" :: "n"(N));
}
__device__ __forceinline__ void ldsm_x4(uint32_t& r0, uint32_t& r1, uint32_t& r2, uint32_t& r3,
                                        uint32_t addr) {
    asm volatile("ldmatrix.sync.aligned.m8n8.x4.shared.b16 {%0,%1,%2,%3}, [%4];"
        : "=r"(r0), "=r"(r1), "=r"(r2), "=r"(r3) : "r"(addr));
}
__device__ __forceinline__ uint32_t lds_u32(uint32_t addr) {
    uint32_t v;
    asm volatile("ld.shared.b32 %0, [%1];" : "=r"(v) : "r"(addr));
    return v;
}
// Sparse 2:4 MMA: D[16o x 8m] += A(16x32 sparse) * B(32x8), f32 acc, selector 0
__device__ __forceinline__ void mma_sp_16832(float& c0, float& c1, float& c2, float& c3,
                                             uint32_t a0, uint32_t a1, uint32_t a2, uint32_t a3,
                                             uint32_t b0, uint32_t b1, uint32_t b2, uint32_t b3,
                                             uint32_t e) {
    asm volatile(
        "mma.sp.sync.aligned.m16n8k32.row.col.f32.f16.f16.f32 "
        "{%0,%1,%2,%3}, {%4,%5,%6,%7}, {%8,%9,%10,%11}, {%0,%1,%2,%3}, %12, 0x0;"
        : "+f"(c0), "+f"(c1), "+f"(c2), "+f"(c3)
        : "r"(a0), "r"(a1), "r"(a2), "r"(a3),
          "r"(b0), "r"(b1), "r"(b2), "r"(b3), "r"(e));
}

// ============================================================
// Kernel 1: x fp32 -> fp16 (row-major) + fp16 transpose copy
// ============================================================
__global__ void convert_transpose_x(const float* __restrict__ x) {
    __shared__ __half st[64 * 72];   // [k_local][m_local] padded
    const int m0 = blockIdx.x * 64;
    const int k0 = blockIdx.y * 64;
    const int tid = threadIdx.x;     // 256
    #pragma unroll
    for (int i = 0; i < 4; i++) {
        int idx = tid + i * 256;             // 0..1023
        int r = idx >> 4, c4 = idx & 15;     // row, float4-col
        float4 v = *reinterpret_cast<const float4*>(x + (size_t)(m0 + r) * K_TOTAL + k0 + c4 * 4);
        __half h0 = __float2half_rn(v.x), h1 = __float2half_rn(v.y);
        __half h2 = __float2half_rn(v.z), h3 = __float2half_rn(v.w);
        __half2 p0 = __halves2half2(h0, h1), p1 = __halves2half2(h2, h3);
        uint2 o;
        o.x = *reinterpret_cast<uint32_t*>(&p0);
        o.y = *reinterpret_cast<uint32_t*>(&p1);
        *reinterpret_cast<uint2*>(&g_xh[(size_t)(m0 + r) * K_TOTAL + k0 + c4 * 4]) = o;
        st[(c4 * 4 + 0) * 72 + r] = h0;
        st[(c4 * 4 + 1) * 72 + r] = h1;
        st[(c4 * 4 + 2) * 72 + r] = h2;
        st[(c4 * 4 + 3) * 72 + r] = h3;
    }
    __syncthreads();
    #pragma unroll
    for (int i = 0; i < 4; i++) {
        int idx = tid + i * 256;
        int kk = idx >> 4, m4 = idx & 15;
        uint2 o;
        __half2 p0 = __halves2half2(st[kk * 72 + m4 * 4 + 0], st[kk * 72 + m4 * 4 + 1]);
        __half2 p1 = __halves2half2(st[kk * 72 + m4 * 4 + 2], st[kk * 72 + m4 * 4 + 3]);
        o.x = *reinterpret_cast<uint32_t*>(&p0);
        o.y = *reinterpret_cast<uint32_t*>(&p1);
        *reinterpret_cast<uint2*>(&g_xt[(size_t)(k0 + kk) * M_TOTAL + m0 + m4 * 4]) = o;
    }
}

// ============================================================
// Kernel 2: W 2:4 compression (values + group codes + residual)
// ============================================================
__global__ void compress_w(const float* __restrict__ w) {
    const int o = blockIdx.x;               // 0..4095
    const int t = threadIdx.x;              // 128
    const float4* wrow = reinterpret_cast<const float4*>(w + (size_t)o * K_TOTAL);
    #pragma unroll
    for (int i = 0; i < 8; i++) {
        int gidx = t + i * 128;             // group index 0..1023
        float4 v4 = wrow[gidx];
        float v[4] = {v4.x, v4.y, v4.z, v4.w};
        int p0 = -1, p1 = -1;
        #pragma unroll
        for (int j = 0; j < 4; j++) {
            if (v[j] != 0.0f) {
                if (p0 < 0) p0 = j;
                else if (p1 < 0) p1 = j;
                else {
                    int b = o >> 7;
                    int slot = atomicAdd(&g_res_cnt[b], 1);
                    if (slot < RES_CAP) {
                        uint2 e;
                        e.x = (uint32_t)(o & 127) | ((uint32_t)(gidx * 4 + j) << 7);
                        e.y = __float_as_uint(v[j]);
                        g_res[b * RES_CAP + slot] = e;
                    }
                }
            }
        }
        int i0, i1;
        if (p0 < 0)      { i0 = 0; i1 = 1; }
        else if (p1 < 0) { if (p0 == 3) { i0 = 2; i1 = 3; } else { i0 = p0; i1 = 3; } }
        else             { i0 = p0; i1 = p1; }
        __half2 hv = __halves2half2(__float2half_rn(v[i0]), __float2half_rn(v[i1]));
        *reinterpret_cast<__half2*>(&g_wv[(size_t)o * (K_TOTAL/2) + gidx * 2]) = hv;
        g_meta4[(size_t)o * (K_TOTAL/4) + gidx] = (uint8_t)(i0 | (i1 << 2));
    }
}

// ============================================================
// Kernel 3: assemble per-lane metadata words
// lane q=lane%4: h=q&1 selects k-half; bits[0:16)=row g, [16:32)=row g+8
// ============================================================
__global__ void assemble_meta() {
    int idx = blockIdx.x * blockDim.x + threadIdx.x;    // 1,048,576
    int og   = idx >> 12;          // 0..255
    int rem  = idx & 4095;
    int ch   = rem >> 5;           // k32 chunk 0..127
    int lane = rem & 31;
    int q = lane & 3;
    int h = q & 1;
    int r  = og * 16 + (lane >> 2);
    int G0 = ch * 8 + h * 4;
    uint32_t wd = 0;
    #pragma unroll
    for (int j = 0; j < 4; j++) {
        wd |= (uint32_t)g_meta4[(size_t)r * (K_TOTAL/4) + G0 + j] << (4 * j);
        wd |= (uint32_t)g_meta4[(size_t)(r + 8) * (K_TOTAL/4) + G0 + j] << (16 + 4 * j);
    }
    g_wm[idx] = wd;
}

// ============================================================
// Kernel 4: sparse GEMM  D[o][m] = W24 . x^T ; out[m][o] = D + bias[o]
// ============================================================
__global__ void __launch_bounds__(NTHREADS, 2) gemm_sp_kernel(
    const float* __restrict__ bias, float* __restrict__ out)
{
    extern __shared__ char smem[];
    const uint32_t smem_u32 = smem_to_u32(smem);
    const int tid  = threadIdx.x;
    const int wid  = tid >> 5;
    const int lane = tid & 31;
    const int wo  = wid >> 1;     // 0..1 o-half (64 rows)
    const int wmh = wid & 1;      // 0..1 m-half (64 cols)

    const int tile_o = (int)(blockIdx.x & 31);
    const int tile_m = (int)(blockIdx.x >> 5);
    const int o0 = tile_o * BO;
    const int m0 = tile_m * BMM;

    float* sbias = reinterpret_cast<float*>(smem);
    for (int i = tid; i < BO; i += NTHREADS) sbias[i] = bias[o0 + i];

    const __half* gX  = g_xh + (size_t)m0 * K_TOTAL;
    const __half* gWV = g_wv + (size_t)o0 * (K_TOTAL/2);
    const char*   gME = reinterpret_cast<const char*>(g_wm) + (size_t)(tile_o * 8) * 16384;

    auto issue_copy = [&](int kt, int stage) {
        const uint32_t sx = smem_u32 + SMEM_BIAS_BYTES + (uint32_t)stage * STAGE_BYTES;
        const uint32_t sv = sx + X_STAGE_BYTES;
        const uint32_t sm = sv + WV_STAGE_BYTES;
        // x: 128 m-rows x 4 chunks16 (64 halves)
        #pragma unroll
        for (int i = 0; i < 8; i++) {
            int idx = tid + i * NTHREADS;
            int rr = idx >> 3, c = idx & 7;
            cp_async16(sx + (uint32_t)rr * X_ROW_BYTES + (uint32_t)c * 16,
                       gX + (size_t)rr * K_TOTAL + kt * BK + c * 8);
        }
        // wv: 128 o-rows x 4 chunks16 (32 stored halves)
        #pragma unroll
        for (int i = 0; i < 4; i++) {
            int idx = tid + i * NTHREADS;
            int rr = idx >> 2, c = idx & 3;
            cp_async16(sv + (uint32_t)rr * WV_ROW_BYTES + (uint32_t)c * 16,
                       gWV + (size_t)rr * (K_TOTAL/2) + kt * 32 + c * 8);
        }
        // meta: 8 og x 256B
        {
            int og = tid >> 4, u = tid & 15;
            cp_async16(sm + (uint32_t)og * 256 + (uint32_t)u * 16,
                       gME + (size_t)og * 16384 + kt * 256 + u * 16);
        }
    };

    float acc[4][8][4];
    #pragma unroll
    for (int mi = 0; mi < 4; mi++)
        #pragma unroll
        for (int nj = 0; nj < 8; nj++)
            #pragma unroll
            for (int c = 0; c < 4; c++) acc[mi][nj][c] = 0.0f;

    #pragma unroll
    for (int s = 0; s < STAGES - 1; s++) { issue_copy(s, s); cp_commit(); }

    for (int kt = 0; kt < KITERS; kt++) {
        cp_wait_group<STAGES - 2>();
        __syncthreads();

        int knext = kt + STAGES - 1;
        if (knext < KITERS) issue_copy(knext, knext % STAGES);
        cp_commit();

        const int stage = kt % STAGES;
        const uint32_t sx = smem_u32 + SMEM_BIAS_BYTES + (uint32_t)stage * STAGE_BYTES;
        const uint32_t sv = sx + X_STAGE_BYTES;
        const uint32_t sm = sv + WV_STAGE_BYTES;

        #pragma unroll
        for (int c = 0; c < 2; c++) {   // two k32 chunks per BK=64
            // B frags: x^T 32k x 8m per nj — one ldsm_x4 each
            uint32_t b[8][4];
            #pragma unroll
            for (int nj = 0; nj < 8; nj++) {
                uint32_t addr = sx + (uint32_t)(wmh * 64 + nj * 8 + (lane & 7)) * X_ROW_BYTES
                              + (uint32_t)c * 64 + (uint32_t)(lane >> 3) * 16;
                ldsm_x4(b[nj][0], b[nj][1], b[nj][2], b[nj][3], addr);
            }
            // A frags (stored 16x16 per mi) + metadata
            uint32_t a[4][4], e[4];
            #pragma unroll
            for (int mi = 0; mi < 4; mi++) {
                uint32_t addr = sv + (uint32_t)(wo * 64 + mi * 16 + (lane & 15)) * WV_ROW_BYTES
                              + (uint32_t)c * 32 + (uint32_t)(lane >> 4) * 16;
                ldsm_x4(a[mi][0], a[mi][1], a[mi][2], a[mi][3], addr);
                e[mi] = lds_u32(sm + (uint32_t)(wo * 4 + mi) * 256 + (uint32_t)c * 128
                                + (uint32_t)lane * 4);
            }
            #pragma unroll
            for (int mi = 0; mi < 4; mi++)
                #pragma unroll
                for (int nj = 0; nj < 8; nj++)
                    mma_sp_16832(acc[mi][nj][0], acc[mi][nj][1], acc[mi][nj][2], acc[mi][nj][3],
                                 a[mi][0], a[mi][1], a[mi][2], a[mi][3],
                                 b[nj][0], b[nj][1], b[nj][2], b[nj][3], e[mi]);
        }
    }
    __syncthreads();

    // ---- epilogue: D[o][m] frags -> staging[m][o] -> out[m][o] + bias[o]
    float* staging = reinterpret_cast<float*>(smem + SMEM_BIAS_BYTES);
    {
        const int g   = lane >> 2;
        const int t2  = (lane & 3) * 2;
        #pragma unroll
        for (int mi = 0; mi < 4; mi++)
            #pragma unroll
            for (int nj = 0; nj < 8; nj++) {
                int o_l = wo * 64 + mi * 16 + g;
                int m_l = wmh * 64 + nj * 8 + t2;
                staging[(size_t)m_l       * EPI_PITCH + o_l]     = acc[mi][nj][0];
                staging[(size_t)(m_l + 1) * EPI_PITCH + o_l]     = acc[mi][nj][1];
                staging[(size_t)m_l       * EPI_PITCH + o_l + 8] = acc[mi][nj][2];
                staging[(size_t)(m_l + 1) * EPI_PITCH + o_l + 8] = acc[mi][nj][3];
            }
    }
    __syncthreads();
    #pragma unroll 4
    for (int idx = tid; idx < BMM * (BO / 4); idx += NTHREADS) {
        int mm = idx >> 5, o4 = idx & 31;
        float4 v = *reinterpret_cast<const float4*>(staging + (size_t)mm * EPI_PITCH + o4 * 4);
        v.x += sbias[o4 * 4 + 0];
        v.y += sbias[o4 * 4 + 1];
        v.z += sbias[o4 * 4 + 2];
        v.w += sbias[o4 * 4 + 3];
        *reinterpret_cast<float4*>(out + (size_t)(m0 + mm) * O_TOTAL + o0 + o4 * 4) = v;
    }
}

// ============================================================
// Kernel 5: residual correction  out[m][o] += sum v * x[m][k]
// grid: (m-splits=8, buckets=32), block 256
// ============================================================
__global__ void residual_correct(float* __restrict__ out) {
    extern __shared__ float corr[];   // [128][129]
    const int b  = blockIdx.y;
    const int t  = threadIdx.x;
    const int w  = t >> 5, lane = t & 31;
    const int n  = min(g_res_cnt[b], RES_CAP);
    const int msplit = blockIdx.x * 2048;

    for (int mc = 0; mc < 16; mc++) {
        const int m_base = msplit + mc * 128;
        for (int i = t; i < 128 * 129; i += 256) corr[i] = 0.0f;
        __syncthreads();
        for (int e = w; e < n; e += 8) {
            uint2 ent = g_res[b * RES_CAP + e];
            int o_l = ent.x & 127;
            int k   = ent.x >> 7;
            float v = __uint_as_float(ent.y);
            const __half* xr = g_xt + (size_t)k * M_TOTAL + m_base;
            #pragma unroll
            for (int j = 0; j < 4; j++) {
                int ml = j * 32 + lane;
                float xv = __half2float(xr[ml]);
                atomicAdd(&corr[ml * 129 + o_l], v * xv);
            }
        }
        __syncthreads();
        for (int i = t; i < 128 * 128; i += 256) {
            int mm = i >> 7, oo = i & 127;
            float c = corr[mm * 129 + oo];
            if (c != 0.0f)
                out[(size_t)(m_base + mm) * O_TOTAL + b * 128 + oo] += c;
        }
        __syncthreads();
    }
}

// ============================================================
// Host launcher
// ============================================================
extern "C" void kernel_launch(void* const* d_in, const int* in_sizes, int n_in,
                              void* d_out, int out_size) {
    const float* x    = (const float*)d_in[0];   // [16384, 4096]
    const float* w    = (const float*)d_in[1];   // [4096, 4096]
    const float* bias = (const float*)d_in[2];   // [4096]
    float* out = (float*)d_out;

    void* cnt_ptr = nullptr;
    cudaGetSymbolAddress(&cnt_ptr, g_res_cnt);
    cudaMemsetAsync(cnt_ptr, 0, RES_BUCKETS * sizeof(int));

    {
        dim3 g(M_TOTAL / 64, K_TOTAL / 64);
        convert_transpose_x<<<g, 256>>>(x);
    }
    compress_w<<<O_TOTAL, 128>>>(w);
    assemble_meta<<<4096, 256>>>();

    static bool attr_set = false;
    if (!attr_set) {
        cudaFuncSetAttribute(gemm_sp_kernel, cudaFuncAttributeMaxDynamicSharedMemorySize,
                             SMEM_TOTAL);
        cudaFuncSetAttribute(residual_correct, cudaFuncAttributeMaxDynamicSharedMemorySize,
                             128 * 129 * 4);
        attr_set = true;
    }
    gemm_sp_kernel<<<GRID_O * GRID_M, NTHREADS, SMEM_TOTAL>>>(bias, out);

    {
        dim3 g(8, RES_BUCKETS);
        residual_correct<<<g, 256, 128 * 129 * 4>>>(out);
    }
}

// round 14
// speedup vs baseline: 5.9835x; 5.9835x over previous
#include <cuda_runtime.h>
#include <cuda_fp16.h>
#include <cstdint>

// ============================================================
// Problem dims (fixed per reference)
// ============================================================
#define M_TOTAL 16384   // B*S
#define N_TOTAL 4096    // D_OUT
#define K_TOTAL 4096    // D_IN

// CTA tile — 2 CTAs/SM (best measured config: R6)
#define BM 128
#define BN 128
#define BK 64
#define STAGES 3
#define KITERS (K_TOTAL / BK)     // 64
#define GRID_N (N_TOTAL / BN)     // 32
#define GRID_M (M_TOTAL / BM)     // 128
#define GROUP_M 16                // tile-order swizzle: M-tiles per N sweep

#define NTHREADS 256              // 8 warps: 2 (M) x 4 (N), warp tile 64x32

// Smem: padded rows -> conflict-free ldmatrix phases.
// 64 halves data + 8 halves pad = 72 halves = 144B row stride.
#define PAD_LD 72
#define ROW_BYTES (PAD_LD * 2)                   // 144
#define A_STAGE_BYTES (BM * ROW_BYTES)           // 18432
#define B_STAGE_BYTES (BN * ROW_BYTES)           // 18432
#define STAGE_BYTES   (A_STAGE_BYTES + B_STAGE_BYTES)   // 36864
#define SMEM_BIAS_BYTES 1024
#define SMEM_TOTAL (SMEM_BIAS_BYTES + STAGES * STAGE_BYTES)  // 111616 (x2 <= 228KB)

// fp16 scratch (static device globals: no runtime allocation)
__device__ __align__(1024) __half g_xh[(size_t)M_TOTAL * K_TOTAL];
__device__ __align__(1024) __half g_wh[(size_t)N_TOTAL * K_TOTAL];

// ============================================================
// PTX helpers (sm_80 base ISA — safe under compute_103)
// ============================================================
__device__ __forceinline__ uint32_t smem_to_u32(const void* p) {
    uint32_t a;
    asm("{ .reg .u64 t; cvta.to.shared.u64 t, %1; cvt.u32.u64 %0, t; }" : "=r"(a) : "l"(p));
    return a;
}

__device__ __forceinline__ void cp_async16(uint32_t saddr, const void* gptr) {
    asm volatile("cp.async.cg.shared.global [%0], [%1], 16;" :: "r"(saddr), "l"(gptr));
}

__device__ __forceinline__ void cp_commit() {
    asm volatile("cp.async.commit_group;");
}

template <int N>
__device__ __forceinline__ void cp_wait_group() {
    asm volatile("cp.async.wait_group %0;" :: "n"(N));
}

__device__ __forceinline__ void ldsm_x4(uint32_t& r0, uint32_t& r1, uint32_t& r2, uint32_t& r3,
                                        uint32_t addr) {
    asm volatile("ldmatrix.sync.aligned.m8n8.x4.shared.b16 {%0,%1,%2,%3}, [%4];"
        : "=r"(r0), "=r"(r1), "=r"(r2), "=r"(r3) : "r"(addr));
}

__device__ __forceinline__ void mma_16816(float& c0, float& c1, float& c2, float& c3,
                                          uint32_t a0, uint32_t a1, uint32_t a2, uint32_t a3,
                                          uint32_t b0, uint32_t b1) {
    asm volatile(
        "mma.sync.aligned.m16n8k16.row.col.f32.f16.f16.f32 "
        "{%0,%1,%2,%3}, {%4,%5,%6,%7}, {%8,%9}, {%0,%1,%2,%3};"
        : "+f"(c0), "+f"(c1), "+f"(c2), "+f"(c3)
        : "r"(a0), "r"(a1), "r"(a2), "r"(a3), "r"(b0), "r"(b1));
}

// ============================================================
// fp32 -> fp16 conversion (single launch, both tensors; DRAM-bound)
// ============================================================
__global__ void f32_to_f16_both(const float4* __restrict__ srcx, uint2* __restrict__ dstx, int n4x,
                                const float4* __restrict__ srcw, uint2* __restrict__ dstw, int n4w) {
    int i = blockIdx.x * blockDim.x + threadIdx.x;
    const float4* s;
    uint2* d;
    int j;
    if (i < n4x) { s = srcx; d = dstx; j = i; }
    else if (i < n4x + n4w) { s = srcw; d = dstw; j = i - n4x; }
    else return;
    float4 v = s[j];
    __half2 a = __floats2half2_rn(v.x, v.y);
    __half2 b = __floats2half2_rn(v.z, v.w);
    uint2 o;
    o.x = *reinterpret_cast<uint32_t*>(&a);
    o.y = *reinterpret_cast<uint32_t*>(&b);
    d[j] = o;
}

// ============================================================
// GEMM: out[M,N] = x[M,K] @ W[N,K]^T + bias
// 3-stage cp.async pipeline, ldmatrix + mma.sync.m16n8k16 (at 99% of
// the legacy-HMMA dispatch ceiling), 2 CTAs/SM, direct frag->gmem epilogue.
// ============================================================
__global__ void __launch_bounds__(NTHREADS, 2) gemm_f16_kernel(
    const __half* __restrict__ xh,
    const __half* __restrict__ wh,
    const float* __restrict__ bias,
    float* __restrict__ out)
{
    extern __shared__ char smem[];
    const uint32_t smem_u32 = smem_to_u32(smem);
    const int tid  = threadIdx.x;
    const int wid  = tid >> 5;
    const int lane = tid & 31;
    const int wm = wid >> 2;       // 0..1  (M warp) -> 64 rows each
    const int wn = wid & 3;        // 0..3  (N warp) -> 32 cols each

    // Swizzled tile order: GROUP_M M-tiles per N sweep (L2 reuse within a wave)
    const int group_size = GROUP_M * GRID_N;
    const int g  = (int)(blockIdx.x / group_size);
    const int r  = (int)(blockIdx.x % group_size);
    const int tile_m = g * GROUP_M + (r % GROUP_M);
    const int tile_n = r / GROUP_M;
    const int m0 = tile_m * BM;
    const int n0 = tile_n * BN;

    // Stage bias tile into smem (covered by first K-loop __syncthreads)
    float* sbias = reinterpret_cast<float*>(smem);
    for (int i = tid; i < BN; i += NTHREADS) sbias[i] = bias[n0 + i];

    const __half* gA_base = xh + (size_t)m0 * K_TOTAL;
    const __half* gW_base = wh + (size_t)n0 * K_TOTAL;

    auto issue_copy = [&](int kt, int stage) {
        const uint32_t sa = smem_u32 + SMEM_BIAS_BYTES + (uint32_t)stage * STAGE_BYTES;
        const uint32_t sb = sa + A_STAGE_BYTES;
        const __half* gA = gA_base + kt * BK;
        const __half* gW = gW_base + kt * BK;
        // A: 128 rows x 8 chunks(16B) = 1024 chunks
        #pragma unroll
        for (int i = 0; i < 4; i++) {
            int idx = tid + i * NTHREADS;
            int rr = idx >> 3, c = idx & 7;
            cp_async16(sa + (uint32_t)rr * ROW_BYTES + (uint32_t)c * 16,
                       gA + (size_t)rr * K_TOTAL + c * 8);
        }
        // B: 128 rows x 8 chunks = 1024 chunks
        #pragma unroll
        for (int i = 0; i < 4; i++) {
            int idx = tid + i * NTHREADS;
            int rr = idx >> 3, c = idx & 7;
            cp_async16(sb + (uint32_t)rr * ROW_BYTES + (uint32_t)c * 16,
                       gW + (size_t)rr * K_TOTAL + c * 8);
        }
    };

    // Accumulators: 4 (m16) x 4 (n8) tiles, 4 floats each = 64 regs
    float acc[4][4][4];
    #pragma unroll
    for (int mi = 0; mi < 4; mi++)
        #pragma unroll
        for (int nj = 0; nj < 4; nj++)
            #pragma unroll
            for (int c = 0; c < 4; c++)
                acc[mi][nj][c] = 0.0f;

    // Pipeline prologue
    #pragma unroll
    for (int s = 0; s < STAGES - 1; s++) {
        issue_copy(s, s);
        cp_commit();
    }

    // ldmatrix lane addressing: rows = base + (lane&15), k-halfword offset = (lane>>4)*16B
    const uint32_t lane_row  = (uint32_t)(lane & 15) * ROW_BYTES;
    const uint32_t lane_koff = (uint32_t)(lane >> 4) * 16;   // bytes

    for (int kt = 0; kt < KITERS; kt++) {
        cp_wait_group<STAGES - 2>();
        __syncthreads();   // single sync per iter: also orders next issue vs prev compute

        int knext = kt + STAGES - 1;
        if (knext < KITERS) issue_copy(knext, knext % STAGES);
        cp_commit();

        const int stage = kt % STAGES;
        const uint32_t sa = smem_u32 + SMEM_BIAS_BYTES + (uint32_t)stage * STAGE_BYTES;
        const uint32_t sb = sa + A_STAGE_BYTES;
        const uint32_t a_base = sa + (uint32_t)(wm * 64) * ROW_BYTES + lane_row + lane_koff;
        const uint32_t b_base = sb + (uint32_t)(wn * 32) * ROW_BYTES + lane_row + lane_koff;

        #pragma unroll
        for (int ks = 0; ks < BK / 16; ks++) {
            const uint32_t koff = (uint32_t)ks * 32;   // 16 halves = 32 bytes
            uint32_t a[4][4], b[2][4];
            #pragma unroll
            for (int mi = 0; mi < 4; mi++)
                ldsm_x4(a[mi][0], a[mi][1], a[mi][2], a[mi][3],
                        a_base + (uint32_t)(mi * 16) * ROW_BYTES + koff);
            #pragma unroll
            for (int nb = 0; nb < 2; nb++)
                ldsm_x4(b[nb][0], b[nb][1], b[nb][2], b[nb][3],
                        b_base + (uint32_t)(nb * 16) * ROW_BYTES + koff);
            // a frag order matches mma A; b: r0=n0-7 k0-7, r1=n8-15 k0-7, r2=n0-7 k8-15, r3=n8-15 k8-15
            #pragma unroll
            for (int mi = 0; mi < 4; mi++)
                #pragma unroll
                for (int nb = 0; nb < 2; nb++) {
                    mma_16816(acc[mi][nb*2][0], acc[mi][nb*2][1], acc[mi][nb*2][2], acc[mi][nb*2][3],
                              a[mi][0], a[mi][1], a[mi][2], a[mi][3], b[nb][0], b[nb][2]);
                    mma_16816(acc[mi][nb*2+1][0], acc[mi][nb*2+1][1], acc[mi][nb*2+1][2], acc[mi][nb*2+1][3],
                              a[mi][0], a[mi][1], a[mi][2], a[mi][3], b[nb][1], b[nb][3]);
                }
        }
    }

    // ---- Epilogue: direct frag -> gmem float2 stores (+bias from smem).
    // m16n8 f32 frag layout: c0,c1 = row (l>>2), cols 2*(l&3)..+1 ; c2,c3 = row+8.
    // Per (mi,nj): a warp writes 8 rows x 32B contiguous quads — sector-efficient.
    {
        const int r_in = lane >> 2;
        const int c_in = (lane & 3) * 2;
        const int row_base = m0 + wm * 64 + r_in;
        const int col_base = wn * 32 + c_in;          // local within BN
        #pragma unroll
        for (int mi = 0; mi < 4; mi++) {
            #pragma unroll
            for (int nj = 0; nj < 4; nj++) {
                int rr = row_base + mi * 16;
                int cc = col_base + nj * 8;
                float b0 = sbias[cc], b1 = sbias[cc + 1];
                *reinterpret_cast<float2*>(out + (size_t)rr * N_TOTAL + n0 + cc)
                    = make_float2(acc[mi][nj][0] + b0, acc[mi][nj][1] + b1);
                *reinterpret_cast<float2*>(out + (size_t)(rr + 8) * N_TOTAL + n0 + cc)
                    = make_float2(acc[mi][nj][2] + b0, acc[mi][nj][3] + b1);
            }
        }
    }
}

// ============================================================
// Host launcher
// ============================================================
extern "C" void kernel_launch(void* const* d_in, const int* in_sizes, int n_in,
                              void* d_out, int out_size) {
    const float* x    = (const float*)d_in[0];   // [16384, 4096]
    const float* w    = (const float*)d_in[1];   // [4096, 4096]
    const float* bias = (const float*)d_in[2];   // [4096]
    float* out = (float*)d_out;

    __half* xh = nullptr;
    __half* wh = nullptr;
    cudaGetSymbolAddress((void**)&xh, g_xh);
    cudaGetSymbolAddress((void**)&wh, g_wh);

    // fp32 -> fp16 conversion (single launch for both tensors)
    int n4x = (int)(((size_t)M_TOTAL * K_TOTAL) / 4);
    int n4w = (int)(((size_t)N_TOTAL * K_TOTAL) / 4);
    int n4  = n4x + n4w;
    f32_to_f16_both<<<(n4 + 255) / 256, 256>>>((const float4*)x, (uint2*)xh, n4x,
                                               (const float4*)w, (uint2*)wh, n4w);

    static bool attr_set = false;
    if (!attr_set) {
        cudaFuncSetAttribute(gemm_f16_kernel, cudaFuncAttributeMaxDynamicSharedMemorySize,
                             SMEM_TOTAL);
        attr_set = true;
    }
    gemm_f16_kernel<<<GRID_M * GRID_N, NTHREADS, SMEM_TOTAL>>>(xh, wh, bias, out);
}

// round 16
// speedup vs baseline: 5.9943x; 1.0018x over previous
#include <cuda_runtime.h>
#include <cuda_fp16.h>
#include <cstdint>

// ============================================================
// Problem dims (fixed per reference)
// ============================================================
#define M_TOTAL 16384   // B*S
#define N_TOTAL 4096    // D_OUT
#define K_TOTAL 4096    // D_IN

// CTA tile — 2 CTAs/SM (best measured config)
#define BM 128
#define BN 128
#define BK 64
#define STAGES 3
#define KITERS (K_TOTAL / BK)     // 64
#define GRID_N (N_TOTAL / BN)     // 32
#define GRID_M (M_TOTAL / BM)     // 128
#define GROUP_M 16                // tile-order swizzle: M-tiles per N sweep

#define NTHREADS 256              // 8 warps: 2 (M) x 4 (N), warp tile 64x32

// Smem: padded rows -> conflict-free ldmatrix phases.
// 64 halves data + 8 halves pad = 72 halves = 144B row stride.
#define PAD_LD 72
#define ROW_BYTES (PAD_LD * 2)                   // 144
#define A_STAGE_BYTES (BM * ROW_BYTES)           // 18432
#define B_STAGE_BYTES (BN * ROW_BYTES)           // 18432
#define STAGE_BYTES   (A_STAGE_BYTES + B_STAGE_BYTES)   // 36864
#define SMEM_BIAS_BYTES 1024
#define SMEM_TOTAL (SMEM_BIAS_BYTES + STAGES * STAGE_BYTES)  // 111616 (x2 <= 228KB)

// fp16 scratch (static device globals: no runtime allocation)
__device__ __align__(1024) __half g_xh[(size_t)M_TOTAL * K_TOTAL];
__device__ __align__(1024) __half g_wh[(size_t)N_TOTAL * K_TOTAL];

// ============================================================
// PTX helpers (sm_80 base ISA — safe under compute_103)
// ============================================================
__device__ __forceinline__ uint32_t smem_to_u32(const void* p) {
    uint32_t a;
    asm("{ .reg .u64 t; cvta.to.shared.u64 t, %1; cvt.u32.u64 %0, t; }" : "=r"(a) : "l"(p));
    return a;
}

__device__ __forceinline__ void cp_async16(uint32_t saddr, const void* gptr) {
    asm volatile("cp.async.cg.shared.global [%0], [%1], 16;" :: "r"(saddr), "l"(gptr));
}

__device__ __forceinline__ void cp_commit() {
    asm volatile("cp.async.commit_group;");
}

template <int N>
__device__ __forceinline__ void cp_wait_group() {
    asm volatile("cp.async.wait_group %0;" :: "n"(N));
}

__device__ __forceinline__ void ldsm_x4(uint32_t& r0, uint32_t& r1, uint32_t& r2, uint32_t& r3,
                                        uint32_t addr) {
    asm volatile("ldmatrix.sync.aligned.m8n8.x4.shared.b16 {%0,%1,%2,%3}, [%4];"
        : "=r"(r0), "=r"(r1), "=r"(r2), "=r"(r3) : "r"(addr));
}

__device__ __forceinline__ void mma_16816(float& c0, float& c1, float& c2, float& c3,
                                          uint32_t a0, uint32_t a1, uint32_t a2, uint32_t a3,
                                          uint32_t b0, uint32_t b1) {
    asm volatile(
        "mma.sync.aligned.m16n8k16.row.col.f32.f16.f16.f32 "
        "{%0,%1,%2,%3}, {%4,%5,%6,%7}, {%8,%9}, {%0,%1,%2,%3};"
        : "+f"(c0), "+f"(c1), "+f"(c2), "+f"(c3)
        : "r"(a0), "r"(a1), "r"(a2), "r"(a3), "r"(b0), "r"(b1));
}

// ============================================================
// fp32 -> fp16 conversion: grid-stride, 4 float4/iter with batched
// loads (MLP=4 covers DRAM latency; fixed SM-resident grid).
// Handles x then w in one launch over the combined index space.
// ============================================================
#define CONV_GRID 1184    // 8 CTAs/SM x 148 SMs
#define CONV_BLK  256

__global__ void f32_to_f16_both(const float4* __restrict__ srcx, uint2* __restrict__ dstx, int n4x,
                                const float4* __restrict__ srcw, uint2* __restrict__ dstw, int n4w) {
    const int n4 = n4x + n4w;
    const int stride = CONV_GRID * CONV_BLK;
    int base = blockIdx.x * CONV_BLK + threadIdx.x;
    // full quads of iterations
    for (; base + 3 * stride < n4; base += 4 * stride) {
        float4 v[4];
        #pragma unroll
        for (int u = 0; u < 4; u++) {
            int i = base + u * stride;
            v[u] = (i < n4x) ? srcx[i] : srcw[i - n4x];
        }
        #pragma unroll
        for (int u = 0; u < 4; u++) {
            int i = base + u * stride;
            __half2 a = __floats2half2_rn(v[u].x, v[u].y);
            __half2 b = __floats2half2_rn(v[u].z, v[u].w);
            uint2 o;
            o.x = *reinterpret_cast<uint32_t*>(&a);
            o.y = *reinterpret_cast<uint32_t*>(&b);
            if (i < n4x) dstx[i] = o; else dstw[i - n4x] = o;
        }
    }
    // remainder
    for (; base < n4; base += stride) {
        float4 v = (base < n4x) ? srcx[base] : srcw[base - n4x];
        __half2 a = __floats2half2_rn(v.x, v.y);
        __half2 b = __floats2half2_rn(v.z, v.w);
        uint2 o;
        o.x = *reinterpret_cast<uint32_t*>(&a);
        o.y = *reinterpret_cast<uint32_t*>(&b);
        if (base < n4x) dstx[base] = o; else dstw[base - n4x] = o;
    }
}

// ============================================================
// GEMM: out[M,N] = x[M,K] @ W[N,K]^T + bias
// 3-stage cp.async pipeline, ldmatrix + mma.sync.m16n8k16 (at the
// legacy-HMMA dispatch ceiling), 2 CTAs/SM, direct frag->gmem epilogue.
// ============================================================
__global__ void __launch_bounds__(NTHREADS, 2) gemm_f16_kernel(
    const __half* __restrict__ xh,
    const __half* __restrict__ wh,
    const float* __restrict__ bias,
    float* __restrict__ out)
{
    extern __shared__ char smem[];
    const uint32_t smem_u32 = smem_to_u32(smem);
    const int tid  = threadIdx.x;
    const int wid  = tid >> 5;
    const int lane = tid & 31;
    const int wm = wid >> 2;       // 0..1  (M warp) -> 64 rows each
    const int wn = wid & 3;        // 0..3  (N warp) -> 32 cols each

    // Swizzled tile order: GROUP_M M-tiles per N sweep (L2 reuse within a wave)
    const int group_size = GROUP_M * GRID_N;
    const int g  = (int)(blockIdx.x / group_size);
    const int r  = (int)(blockIdx.x % group_size);
    const int tile_m = g * GROUP_M + (r % GROUP_M);
    const int tile_n = r / GROUP_M;
    const int m0 = tile_m * BM;
    const int n0 = tile_n * BN;

    // Stage bias tile into smem (covered by first K-loop __syncthreads)
    float* sbias = reinterpret_cast<float*>(smem);
    for (int i = tid; i < BN; i += NTHREADS) sbias[i] = bias[n0 + i];

    const __half* gA_base = xh + (size_t)m0 * K_TOTAL;
    const __half* gW_base = wh + (size_t)n0 * K_TOTAL;

    auto issue_copy = [&](int kt, int stage) {
        const uint32_t sa = smem_u32 + SMEM_BIAS_BYTES + (uint32_t)stage * STAGE_BYTES;
        const uint32_t sb = sa + A_STAGE_BYTES;
        const __half* gA = gA_base + kt * BK;
        const __half* gW = gW_base + kt * BK;
        #pragma unroll
        for (int i = 0; i < 4; i++) {
            int idx = tid + i * NTHREADS;
            int rr = idx >> 3, c = idx & 7;
            cp_async16(sa + (uint32_t)rr * ROW_BYTES + (uint32_t)c * 16,
                       gA + (size_t)rr * K_TOTAL + c * 8);
        }
        #pragma unroll
        for (int i = 0; i < 4; i++) {
            int idx = tid + i * NTHREADS;
            int rr = idx >> 3, c = idx & 7;
            cp_async16(sb + (uint32_t)rr * ROW_BYTES + (uint32_t)c * 16,
                       gW + (size_t)rr * K_TOTAL + c * 8);
        }
    };

    // Accumulators: 4 (m16) x 4 (n8) tiles, 4 floats each = 64 regs
    float acc[4][4][4];
    #pragma unroll
    for (int mi = 0; mi < 4; mi++)
        #pragma unroll
        for (int nj = 0; nj < 4; nj++)
            #pragma unroll
            for (int c = 0; c < 4; c++)
                acc[mi][nj][c] = 0.0f;

    // Pipeline prologue
    #pragma unroll
    for (int s = 0; s < STAGES - 1; s++) {
        issue_copy(s, s);
        cp_commit();
    }

    const uint32_t lane_row  = (uint32_t)(lane & 15) * ROW_BYTES;
    const uint32_t lane_koff = (uint32_t)(lane >> 4) * 16;   // bytes

    for (int kt = 0; kt < KITERS; kt++) {
        cp_wait_group<STAGES - 2>();
        __syncthreads();   // single sync per iter: also orders next issue vs prev compute

        int knext = kt + STAGES - 1;
        if (knext < KITERS) issue_copy(knext, knext % STAGES);
        cp_commit();

        const int stage = kt % STAGES;
        const uint32_t sa = smem_u32 + SMEM_BIAS_BYTES + (uint32_t)stage * STAGE_BYTES;
        const uint32_t sb = sa + A_STAGE_BYTES;
        const uint32_t a_base = sa + (uint32_t)(wm * 64) * ROW_BYTES + lane_row + lane_koff;
        const uint32_t b_base = sb + (uint32_t)(wn * 32) * ROW_BYTES + lane_row + lane_koff;

        #pragma unroll
        for (int ks = 0; ks < BK / 16; ks++) {
            const uint32_t koff = (uint32_t)ks * 32;   // 16 halves = 32 bytes
            uint32_t a[4][4], b[2][4];
            #pragma unroll
            for (int mi = 0; mi < 4; mi++)
                ldsm_x4(a[mi][0], a[mi][1], a[mi][2], a[mi][3],
                        a_base + (uint32_t)(mi * 16) * ROW_BYTES + koff);
            #pragma unroll
            for (int nb = 0; nb < 2; nb++)
                ldsm_x4(b[nb][0], b[nb][1], b[nb][2], b[nb][3],
                        b_base + (uint32_t)(nb * 16) * ROW_BYTES + koff);
            #pragma unroll
            for (int mi = 0; mi < 4; mi++)
                #pragma unroll
                for (int nb = 0; nb < 2; nb++) {
                    mma_16816(acc[mi][nb*2][0], acc[mi][nb*2][1], acc[mi][nb*2][2], acc[mi][nb*2][3],
                              a[mi][0], a[mi][1], a[mi][2], a[mi][3], b[nb][0], b[nb][2]);
                    mma_16816(acc[mi][nb*2+1][0], acc[mi][nb*2+1][1], acc[mi][nb*2+1][2], acc[mi][nb*2+1][3],
                              a[mi][0], a[mi][1], a[mi][2], a[mi][3], b[nb][1], b[nb][3]);
                }
        }
    }

    // ---- Epilogue: direct frag -> gmem float2 stores (+bias from smem).
    // m16n8 f32 frag layout: c0,c1 = row (l>>2), cols 2*(l&3)..+1 ; c2,c3 = row+8.
    {
        const int r_in = lane >> 2;
        const int c_in = (lane & 3) * 2;
        const int row_base = m0 + wm * 64 + r_in;
        const int col_base = wn * 32 + c_in;
        #pragma unroll
        for (int mi = 0; mi < 4; mi++) {
            #pragma unroll
            for (int nj = 0; nj < 4; nj++) {
                int rr = row_base + mi * 16;
                int cc = col_base + nj * 8;
                float b0 = sbias[cc], b1 = sbias[cc + 1];
                *reinterpret_cast<float2*>(out + (size_t)rr * N_TOTAL + n0 + cc)
                    = make_float2(acc[mi][nj][0] + b0, acc[mi][nj][1] + b1);
                *reinterpret_cast<float2*>(out + (size_t)(rr + 8) * N_TOTAL + n0 + cc)
                    = make_float2(acc[mi][nj][2] + b0, acc[mi][nj][3] + b1);
            }
        }
    }
}

// ============================================================
// Host launcher (single stream — harness-legal)
// ============================================================
extern "C" void kernel_launch(void* const* d_in, const int* in_sizes, int n_in,
                              void* d_out, int out_size) {
    const float* x    = (const float*)d_in[0];   // [16384, 4096]
    const float* w    = (const float*)d_in[1];   // [4096, 4096]
    const float* bias = (const float*)d_in[2];   // [4096]
    float* out = (float*)d_out;

    __half* xh = nullptr;
    __half* wh = nullptr;
    cudaGetSymbolAddress((void**)&xh, g_xh);
    cudaGetSymbolAddress((void**)&wh, g_wh);

    // fp32 -> fp16 conversion (single grid-stride launch, both tensors)
    int n4x = (int)(((size_t)M_TOTAL * K_TOTAL) / 4);
    int n4w = (int)(((size_t)N_TOTAL * K_TOTAL) / 4);
    f32_to_f16_both<<<CONV_GRID, CONV_BLK>>>((const float4*)x, (uint2*)xh, n4x,
                                             (const float4*)w, (uint2*)wh, n4w);

    static bool attr_set = false;
    if (!attr_set) {
        cudaFuncSetAttribute(gemm_f16_kernel, cudaFuncAttributeMaxDynamicSharedMemorySize,
                             SMEM_TOTAL);
        attr_set = true;
    }
    gemm_f16_kernel<<<GRID_M * GRID_N, NTHREADS, SMEM_TOTAL>>>(xh, wh, bias, out);
}

// round 17
// speedup vs baseline: 5.9992x; 1.0008x over previous
#include <cuda_runtime.h>
#include <cuda_fp16.h>
#include <cstdint>

// ============================================================
// FINAL KERNEL — converged at the combined hardware floor:
//   GEMM  ≈ 1628 us  (legacy-HMMA dispatch ceiling, ~13 cyc/mma.16816/SMSP,
//                     validated across 6 structural variants; tensor=55.3%)
//   convert ≈ 78 us  (DRAM-bound at ~74% of 8 TB/s spec)
// tcgen05: toolchain-gated (compute_103, no 'a' features)
// mma.sp:  ALU-emulated on this path (10x slower, measured)
// multi-stream overlap: forbidden (stream creation trips alloc guard)
// ============================================================

#define M_TOTAL 16384   // B*S
#define N_TOTAL 4096    // D_OUT
#define K_TOTAL 4096    // D_IN

// CTA tile — 2 CTAs/SM (best measured config)
#define BM 128
#define BN 128
#define BK 64
#define STAGES 3
#define KITERS (K_TOTAL / BK)     // 64
#define GRID_N (N_TOTAL / BN)     // 32
#define GRID_M (M_TOTAL / BM)     // 128
#define GROUP_M 16                // tile-order swizzle: M-tiles per N sweep

#define NTHREADS 256              // 8 warps: 2 (M) x 4 (N), warp tile 64x32

// Smem: padded rows -> conflict-free ldmatrix phases.
// 64 halves data + 8 halves pad = 72 halves = 144B row stride.
#define PAD_LD 72
#define ROW_BYTES (PAD_LD * 2)                   // 144
#define A_STAGE_BYTES (BM * ROW_BYTES)           // 18432
#define B_STAGE_BYTES (BN * ROW_BYTES)           // 18432
#define STAGE_BYTES   (A_STAGE_BYTES + B_STAGE_BYTES)   // 36864
#define SMEM_BIAS_BYTES 1024
#define SMEM_TOTAL (SMEM_BIAS_BYTES + STAGES * STAGE_BYTES)  // 111616 (x2 <= 228KB)

// fp16 scratch (static device globals: no runtime allocation)
__device__ __align__(1024) __half g_xh[(size_t)M_TOTAL * K_TOTAL];
__device__ __align__(1024) __half g_wh[(size_t)N_TOTAL * K_TOTAL];

// ============================================================
// PTX helpers (sm_80 base ISA — safe under compute_103)
// ============================================================
__device__ __forceinline__ uint32_t smem_to_u32(const void* p) {
    uint32_t a;
    asm("{ .reg .u64 t; cvta.to.shared.u64 t, %1; cvt.u32.u64 %0, t; }" : "=r"(a) : "l"(p));
    return a;
}

__device__ __forceinline__ void cp_async16(uint32_t saddr, const void* gptr) {
    asm volatile("cp.async.cg.shared.global [%0], [%1], 16;" :: "r"(saddr), "l"(gptr));
}

__device__ __forceinline__ void cp_commit() {
    asm volatile("cp.async.commit_group;");
}

template <int N>
__device__ __forceinline__ void cp_wait_group() {
    asm volatile("cp.async.wait_group %0;" :: "n"(N));
}

__device__ __forceinline__ void ldsm_x4(uint32_t& r0, uint32_t& r1, uint32_t& r2, uint32_t& r3,
                                        uint32_t addr) {
    asm volatile("ldmatrix.sync.aligned.m8n8.x4.shared.b16 {%0,%1,%2,%3}, [%4];"
        : "=r"(r0), "=r"(r1), "=r"(r2), "=r"(r3) : "r"(addr));
}

__device__ __forceinline__ void mma_16816(float& c0, float& c1, float& c2, float& c3,
                                          uint32_t a0, uint32_t a1, uint32_t a2, uint32_t a3,
                                          uint32_t b0, uint32_t b1) {
    asm volatile(
        "mma.sync.aligned.m16n8k16.row.col.f32.f16.f16.f32 "
        "{%0,%1,%2,%3}, {%4,%5,%6,%7}, {%8,%9}, {%0,%1,%2,%3};"
        : "+f"(c0), "+f"(c1), "+f"(c2), "+f"(c3)
        : "r"(a0), "r"(a1), "r"(a2), "r"(a3), "r"(b0), "r"(b1));
}

// ============================================================
// fp32 -> fp16 conversion: grid-stride, 4 float4/iter with batched
// loads (MLP=4 covers DRAM latency; fixed SM-resident grid).
// ============================================================
#define CONV_GRID 1184    // 8 CTAs/SM x 148 SMs
#define CONV_BLK  256

__global__ void f32_to_f16_both(const float4* __restrict__ srcx, uint2* __restrict__ dstx, int n4x,
                                const float4* __restrict__ srcw, uint2* __restrict__ dstw, int n4w) {
    const int n4 = n4x + n4w;
    const int stride = CONV_GRID * CONV_BLK;
    int base = blockIdx.x * CONV_BLK + threadIdx.x;
    for (; base + 3 * stride < n4; base += 4 * stride) {
        float4 v[4];
        #pragma unroll
        for (int u = 0; u < 4; u++) {
            int i = base + u * stride;
            v[u] = (i < n4x) ? srcx[i] : srcw[i - n4x];
        }
        #pragma unroll
        for (int u = 0; u < 4; u++) {
            int i = base + u * stride;
            __half2 a = __floats2half2_rn(v[u].x, v[u].y);
            __half2 b = __floats2half2_rn(v[u].z, v[u].w);
            uint2 o;
            o.x = *reinterpret_cast<uint32_t*>(&a);
            o.y = *reinterpret_cast<uint32_t*>(&b);
            if (i < n4x) dstx[i] = o; else dstw[i - n4x] = o;
        }
    }
    for (; base < n4; base += stride) {
        float4 v = (base < n4x) ? srcx[base] : srcw[base - n4x];
        __half2 a = __floats2half2_rn(v.x, v.y);
        __half2 b = __floats2half2_rn(v.z, v.w);
        uint2 o;
        o.x = *reinterpret_cast<uint32_t*>(&a);
        o.y = *reinterpret_cast<uint32_t*>(&b);
        if (base < n4x) dstx[base] = o; else dstw[base - n4x] = o;
    }
}

// ============================================================
// GEMM: out[M,N] = x[M,K] @ W[N,K]^T + bias
// 3-stage cp.async pipeline, ldmatrix + mma.sync.m16n8k16 (at the
// legacy-HMMA dispatch ceiling), 2 CTAs/SM, direct frag->gmem epilogue.
// ============================================================
__global__ void __launch_bounds__(NTHREADS, 2) gemm_f16_kernel(
    const __half* __restrict__ xh,
    const __half* __restrict__ wh,
    const float* __restrict__ bias,
    float* __restrict__ out)
{
    extern __shared__ char smem[];
    const uint32_t smem_u32 = smem_to_u32(smem);
    const int tid  = threadIdx.x;
    const int wid  = tid >> 5;
    const int lane = tid & 31;
    const int wm = wid >> 2;       // 0..1  (M warp) -> 64 rows each
    const int wn = wid & 3;        // 0..3  (N warp) -> 32 cols each

    // Swizzled tile order: GROUP_M M-tiles per N sweep (L2 reuse within a wave)
    const int group_size = GROUP_M * GRID_N;
    const int g  = (int)(blockIdx.x / group_size);
    const int r  = (int)(blockIdx.x % group_size);
    const int tile_m = g * GROUP_M + (r % GROUP_M);
    const int tile_n = r / GROUP_M;
    const int m0 = tile_m * BM;
    const int n0 = tile_n * BN;

    // Stage bias tile into smem (covered by first K-loop __syncthreads)
    float* sbias = reinterpret_cast<float*>(smem);
    for (int i = tid; i < BN; i += NTHREADS) sbias[i] = bias[n0 + i];

    const __half* gA_base = xh + (size_t)m0 * K_TOTAL;
    const __half* gW_base = wh + (size_t)n0 * K_TOTAL;

    auto issue_copy = [&](int kt, int stage) {
        const uint32_t sa = smem_u32 + SMEM_BIAS_BYTES + (uint32_t)stage * STAGE_BYTES;
        const uint32_t sb = sa + A_STAGE_BYTES;
        const __half* gA = gA_base + kt * BK;
        const __half* gW = gW_base + kt * BK;
        #pragma unroll
        for (int i = 0; i < 4; i++) {
            int idx = tid + i * NTHREADS;
            int rr = idx >> 3, c = idx & 7;
            cp_async16(sa + (uint32_t)rr * ROW_BYTES + (uint32_t)c * 16,
                       gA + (size_t)rr * K_TOTAL + c * 8);
        }
        #pragma unroll
        for (int i = 0; i < 4; i++) {
            int idx = tid + i * NTHREADS;
            int rr = idx >> 3, c = idx & 7;
            cp_async16(sb + (uint32_t)rr * ROW_BYTES + (uint32_t)c * 16,
                       gW + (size_t)rr * K_TOTAL + c * 8);
        }
    };

    // Accumulators: 4 (m16) x 4 (n8) tiles, 4 floats each = 64 regs
    float acc[4][4][4];
    #pragma unroll
    for (int mi = 0; mi < 4; mi++)
        #pragma unroll
        for (int nj = 0; nj < 4; nj++)
            #pragma unroll
            for (int c = 0; c < 4; c++)
                acc[mi][nj][c] = 0.0f;

    // Pipeline prologue
    #pragma unroll
    for (int s = 0; s < STAGES - 1; s++) {
        issue_copy(s, s);
        cp_commit();
    }

    const uint32_t lane_row  = (uint32_t)(lane & 15) * ROW_BYTES;
    const uint32_t lane_koff = (uint32_t)(lane >> 4) * 16;   // bytes

    for (int kt = 0; kt < KITERS; kt++) {
        cp_wait_group<STAGES - 2>();
        __syncthreads();   // single sync per iter: also orders next issue vs prev compute

        int knext = kt + STAGES - 1;
        if (knext < KITERS) issue_copy(knext, knext % STAGES);
        cp_commit();

        const int stage = kt % STAGES;
        const uint32_t sa = smem_u32 + SMEM_BIAS_BYTES + (uint32_t)stage * STAGE_BYTES;
        const uint32_t sb = sa + A_STAGE_BYTES;
        const uint32_t a_base = sa + (uint32_t)(wm * 64) * ROW_BYTES + lane_row + lane_koff;
        const uint32_t b_base = sb + (uint32_t)(wn * 32) * ROW_BYTES + lane_row + lane_koff;

        #pragma unroll
        for (int ks = 0; ks < BK / 16; ks++) {
            const uint32_t koff = (uint32_t)ks * 32;   // 16 halves = 32 bytes
            uint32_t a[4][4], b[2][4];
            #pragma unroll
            for (int mi = 0; mi < 4; mi++)
                ldsm_x4(a[mi][0], a[mi][1], a[mi][2], a[mi][3],
                        a_base + (uint32_t)(mi * 16) * ROW_BYTES + koff);
            #pragma unroll
            for (int nb = 0; nb < 2; nb++)
                ldsm_x4(b[nb][0], b[nb][1], b[nb][2], b[nb][3],
                        b_base + (uint32_t)(nb * 16) * ROW_BYTES + koff);
            #pragma unroll
            for (int mi = 0; mi < 4; mi++)
                #pragma unroll
                for (int nb = 0; nb < 2; nb++) {
                    mma_16816(acc[mi][nb*2][0], acc[mi][nb*2][1], acc[mi][nb*2][2], acc[mi][nb*2][3],
                              a[mi][0], a[mi][1], a[mi][2], a[mi][3], b[nb][0], b[nb][2]);
                    mma_16816(acc[mi][nb*2+1][0], acc[mi][nb*2+1][1], acc[mi][nb*2+1][2], acc[mi][nb*2+1][3],
                              a[mi][0], a[mi][1], a[mi][2], a[mi][3], b[nb][1], b[nb][3]);
                }
        }
    }

    // ---- Epilogue: direct frag -> gmem float2 stores (+bias from smem).
    // m16n8 f32 frag layout: c0,c1 = row (l>>2), cols 2*(l&3)..+1 ; c2,c3 = row+8.
    {
        const int r_in = lane >> 2;
        const int c_in = (lane & 3) * 2;
        const int row_base = m0 + wm * 64 + r_in;
        const int col_base = wn * 32 + c_in;
        #pragma unroll
        for (int mi = 0; mi < 4; mi++) {
            #pragma unroll
            for (int nj = 0; nj < 4; nj++) {
                int rr = row_base + mi * 16;
                int cc = col_base + nj * 8;
                float b0 = sbias[cc], b1 = sbias[cc + 1];
                *reinterpret_cast<float2*>(out + (size_t)rr * N_TOTAL + n0 + cc)
                    = make_float2(acc[mi][nj][0] + b0, acc[mi][nj][1] + b1);
                *reinterpret_cast<float2*>(out + (size_t)(rr + 8) * N_TOTAL + n0 + cc)
                    = make_float2(acc[mi][nj][2] + b0, acc[mi][nj][3] + b1);
            }
        }
    }
}

// ============================================================
// Host launcher (single stream — harness-legal)
// ============================================================
extern "C" void kernel_launch(void* const* d_in, const int* in_sizes, int n_in,
                              void* d_out, int out_size) {
    const float* x    = (const float*)d_in[0];   // [16384, 4096]
    const float* w    = (const float*)d_in[1];   // [4096, 4096]
    const float* bias = (const float*)d_in[2];   // [4096]
    float* out = (float*)d_out;

    __half* xh = nullptr;
    __half* wh = nullptr;
    cudaGetSymbolAddress((void**)&xh, g_xh);
    cudaGetSymbolAddress((void**)&wh, g_wh);

    // fp32 -> fp16 conversion (single grid-stride launch, both tensors)
    int n4x = (int)(((size_t)M_TOTAL * K_TOTAL) / 4);
    int n4w = (int)(((size_t)N_TOTAL * K_TOTAL) / 4);
    f32_to_f16_both<<<CONV_GRID, CONV_BLK>>>((const float4*)x, (uint2*)xh, n4x,
                                             (const float4*)w, (uint2*)wh, n4w);

    static bool attr_set = false;
    if (!attr_set) {
        cudaFuncSetAttribute(gemm_f16_kernel, cudaFuncAttributeMaxDynamicSharedMemorySize,
                             SMEM_TOTAL);
        attr_set = true;
    }
    gemm_f16_kernel<<<GRID_M * GRID_N, NTHREADS, SMEM_TOTAL>>>(xh, wh, bias, out);
}